// round 7
// baseline (speedup 1.0000x reference)
#include <cuda_runtime.h>
#include <math.h>

// LogSparseAttention: B=2, L=S=2048, H=8, E=D=64.
// Mask: row l<22 -> cols 0..l ; row l>=22 -> {l-10..l} U {l-10-2^i, i=0..10, >=0}.
// R7: R6 structure (4 rows/warp, shared window broadcast loads) + paired-column
//     butterfly multi-reduce in the score phase: 2 columns per 4 shuffles
//     instead of 2x3. Score shuffles 75 -> 51.

#define BB 2
#define LL 2048
#define HH 8
#define EE 64
#define DD 64
#define QSCALE 0.125f
#define FULL 0xffffffffu
#define KSTRIDE (HH * EE)   // 512 floats between consecutive K/V rows of same (b,h)

typedef unsigned long long u64;

__device__ __forceinline__ u64 fma2(u64 a, u64 b, u64 c) {
    u64 r; asm("fma.rn.f32x2 %0, %1, %2, %3;" : "=l"(r) : "l"(a), "l"(b), "l"(c));
    return r;
}
__device__ __forceinline__ u64 mul2(u64 a, u64 b) {
    u64 r; asm("mul.rn.f32x2 %0, %1, %2;" : "=l"(r) : "l"(a), "l"(b));
    return r;
}
__device__ __forceinline__ u64 pack2(float x, float y) {
    u64 r; asm("mov.b64 %0, {%1, %2};" : "=l"(r) : "f"(x), "f"(y));
    return r;
}
__device__ __forceinline__ void unpack2(u64 v, float& x, float& y) {
    asm("mov.b64 {%0, %1}, %2;" : "=f"(x), "=f"(y) : "l"(v));
}

__global__ __launch_bounds__(256, 4)
void logsparse_attn_kernel(const float* __restrict__ Q,
                           const float* __restrict__ K,
                           const float* __restrict__ V,
                           float* __restrict__ O)
{
    const int warp = threadIdx.x >> 5;
    const int lane = threadIdx.x & 31;
    const int sub  = lane & 7;
    const int lanebase = lane & 24;

    const int gid   = blockIdx.x * 8 + warp;
    const int lbase = (gid & 511) << 2;
    const int bh    = gid >> 9;
    const int h     = bh & (HH - 1);
    const int b     = bh >> 3;
    const int l     = lbase + (lane >> 3);
    const bool causal = (l < 22);

    const float* Kbh = K + (b * (LL * HH) + h) * EE;
    const float* Vbh = V + (b * (LL * HH) + h) * DD;

    // ---- q for own row, pre-scaled, packed ----
    const int qoff = ((b * LL + l) * HH + h) * EE;
    const ulonglong2* qp = (const ulonglong2*)(Q + qoff);
    ulonglong2 qa = qp[sub];
    ulonglong2 qb = qp[8 + sub];
    const u64 qs = pack2(QSCALE, QSCALE);
    qa.x = mul2(qa.x, qs); qa.y = mul2(qa.y, qs);
    qb.x = mul2(qb.x, qs); qb.y = mul2(qb.y, qs);

    float s0 = -INFINITY, s1 = -INFINITY, s2 = -INFINITY;

    // per-lane partial dot of q with K row at cc
    #define KDOT(cc, OUT) do {                                              \
        const ulonglong2* kp_ = (const ulonglong2*)(Kbh + (cc) * KSTRIDE);  \
        ulonglong2 ka_ = kp_[sub];                                          \
        ulonglong2 kb_ = kp_[8 + sub];                                      \
        u64 d_ = mul2(qa.x, ka_.x);                                         \
        d_ = fma2(qa.y, ka_.y, d_);                                         \
        d_ = fma2(qb.x, kb_.x, d_);                                         \
        d_ = fma2(qb.y, kb_.y, d_);                                         \
        float px_, py_; unpack2(d_, px_, py_);                              \
        OUT = px_ + py_;                                                    \
    } while (0)

    // paired butterfly reduce: partA/partB (8-lane partials) -> sumA/sumB in all lanes
    #define PAIR_REDUCE(partA, partB, sumA, sumB) do {                      \
        float keep_ = (sub & 1) ? (partB) : (partA);                        \
        float send_ = (sub & 1) ? (partA) : (partB);                        \
        float live_ = keep_ + __shfl_xor_sync(FULL, send_, 1);              \
        live_ += __shfl_xor_sync(FULL, live_, 2);                           \
        live_ += __shfl_xor_sync(FULL, live_, 4);                           \
        float other_ = __shfl_xor_sync(FULL, live_, 1);                     \
        sumA = (sub & 1) ? other_ : live_;                                  \
        sumB = (sub & 1) ? live_ : other_;                                  \
    } while (0)

    #define PLACE(c_, sum_) do {                                            \
        int  j_   = causal ? (c_) : ((c_) - l + 21);                        \
        bool act_ = ((c_) >= 0) &&                                          \
                    (causal ? ((c_) <= l) : (j_ >= 11 && j_ <= 21));        \
        if (act_ && sub == (j_ & 7)) {                                      \
            int jr_ = j_ >> 3;                                              \
            if (jr_ == 0) s0 = sum_; else if (jr_ == 1) s1 = sum_;          \
            else s2 = sum_;                                                 \
        }                                                                   \
    } while (0)

    // ---- window scores: cols lbase-10 .. lbase+3, 2 cols per reduce ----
#pragma unroll
    for (int t2 = 0; t2 < 7; ++t2) {
        int cA = lbase - 10 + 2 * t2;
        int cB = cA + 1;
        int ccA = (cA < 0) ? 0 : cA;
        int ccB = (cB < 0) ? 0 : cB;
        float pA, pB;
        KDOT(ccA, pA);
        KDOT(ccB, pB);
        float sA, sB;
        PAIR_REDUCE(pA, pB, sA, sB);
        PLACE(cA, sA);
        PLACE(cB, sB);
    }

    // ---- log scores: slots j=10-i, row-private cols; 5 pairs + 1 single ----
    #define LOGCOL(i_, j_, c_, act_) do {                                   \
        if (causal) { act_ = ((j_) <= l); c_ = act_ ? (j_) : 0; }           \
        else { c_ = l - 10 - (1 << (i_)); act_ = (c_ >= 0);                 \
               c_ = act_ ? c_ : 0; }                                        \
    } while (0)

    #define LOGPLACE(j_, act_, sum_) do {                                   \
        if ((act_) && sub == ((j_) & 7)) {                                  \
            if (((j_) >> 3) == 0) s0 = sum_; else s1 = sum_;                \
        }                                                                   \
    } while (0)

#pragma unroll
    for (int ip = 0; ip < 5; ++ip) {
        const int iA = 2 * ip,  jA = 10 - iA;
        const int iB = iA + 1,  jB = 10 - iB;
        int cA, cB; bool aA, aB;
        LOGCOL(iA, jA, cA, aA);
        LOGCOL(iB, jB, cB, aB);
        float pA, pB;
        KDOT(cA, pA);
        KDOT(cB, pB);
        float sA, sB;
        PAIR_REDUCE(pA, pB, sA, sB);
        LOGPLACE(jA, aA, sA);
        LOGPLACE(jB, aB, sB);
    }
    {   // single slot j=0 (i=10)
        int c; bool a;
        LOGCOL(10, 0, c, a);
        float pt;
        KDOT(c, pt);
        pt += __shfl_xor_sync(FULL, pt, 1);
        pt += __shfl_xor_sync(FULL, pt, 2);
        pt += __shfl_xor_sync(FULL, pt, 4);
        LOGPLACE(0, a, pt);
    }

    // ---- per-row softmax (width-8 group reduce) ----
    float m = fmaxf(s0, fmaxf(s1, s2));
    m = fmaxf(m, __shfl_xor_sync(FULL, m, 1));
    m = fmaxf(m, __shfl_xor_sync(FULL, m, 2));
    m = fmaxf(m, __shfl_xor_sync(FULL, m, 4));
    float p0 = __expf(s0 - m), p1 = __expf(s1 - m), p2 = __expf(s2 - m);
    float sum = p0 + p1 + p2;
    sum += __shfl_xor_sync(FULL, sum, 1);
    sum += __shfl_xor_sync(FULL, sum, 2);
    sum += __shfl_xor_sync(FULL, sum, 4);
    float inv = __frcp_rn(sum);
    p0 *= inv; p1 *= inv; p2 *= inv;

    // ---- V accumulation ----
    u64 a00 = pack2(0.f, 0.f), a01 = a00, a10 = a00, a11 = a00;

    // window V (shared cols, broadcast loads)
#pragma unroll
    for (int t = 0; t < 14; ++t) {
        int c  = lbase - 10 + t;
        int cc = (c < 0) ? 0 : c;
        const ulonglong2* vp = (const ulonglong2*)(Vbh + cc * KSTRIDE);
        ulonglong2 va = vp[sub];
        ulonglong2 vb = vp[8 + sub];
        int  j   = causal ? c : (c - l + 21);
        bool act = (c >= 0) && (causal ? (c <= l) : (j >= 11 && j <= 21));
        int  jj  = act ? j : 0;
        int  jr  = jj >> 3;
        float psel = (jr == 0) ? p0 : ((jr == 1) ? p1 : p2);
        float pj = __shfl_sync(FULL, psel, lanebase | (jj & 7));
        pj = act ? pj : 0.0f;
        u64 pj2 = pack2(pj, pj);
        a00 = fma2(pj2, va.x, a00); a01 = fma2(pj2, va.y, a01);
        a10 = fma2(pj2, vb.x, a10); a11 = fma2(pj2, vb.y, a11);
    }

    // log V (row-private cols; causal rows deduped against window loop)
#pragma unroll
    for (int i = 0; i < 11; ++i) {
        const int j = 10 - i;
        int c; bool act;
        if (causal) { act = (j <= l) && (j < lbase - 10); c = (j <= l) ? j : 0; }
        else        { c = l - 10 - (1 << i); act = (c >= 0); c = act ? c : 0; }
        const ulonglong2* vp = (const ulonglong2*)(Vbh + c * KSTRIDE);
        ulonglong2 va = vp[sub];
        ulonglong2 vb = vp[8 + sub];
        float psel = (j <= 7) ? p0 : p1;
        float pj = __shfl_sync(FULL, psel, lanebase | (j & 7));
        pj = act ? pj : 0.0f;
        u64 pj2 = pack2(pj, pj);
        a00 = fma2(pj2, va.x, a00); a01 = fma2(pj2, va.y, a01);
        a10 = fma2(pj2, vb.x, a10); a11 = fma2(pj2, vb.y, a11);
    }

    // ---- store own row ----
    float x0, x1, x2, x3;
    float4* op = (float4*)(O + qoff);
    unpack2(a00, x0, x1); unpack2(a01, x2, x3);
    op[sub] = make_float4(x0, x1, x2, x3);
    unpack2(a10, x0, x1); unpack2(a11, x2, x3);
    op[8 + sub] = make_float4(x0, x1, x2, x3);
}

extern "C" void kernel_launch(void* const* d_in, const int* in_sizes, int n_in,
                              void* d_out, int out_size) {
    const float* Q = (const float*)d_in[0];
    const float* K = (const float*)d_in[1];
    const float* V = (const float*)d_in[2];
    float* O = (float*)d_out;

    dim3 grid(BB * HH * (LL / 4) / 8);   // 1024 blocks, 8 warps each
    logsparse_attn_kernel<<<grid, 256>>>(Q, K, V, O);
}

// round 8
// speedup vs baseline: 1.4087x; 1.4087x over previous
#include <cuda_runtime.h>
#include <math.h>

// LogSparseAttention: B=2, L=S=2048, H=8, E=D=64.
// Mask: row l<22 -> cols 0..l ; row l>=22 -> {l-10..l} U {l-10-2^i, i=0..10, >=0}.
// R8 = R6 (4 rows/warp, shared window broadcast loads) with the score phase
//      re-staged for load/latency overlap:
//        stage 1: all 22 log-K LDGs + FFMA partials (no shuffles -> batched)
//        stage 2: window loop (loads + shuffles) hides log-load completion
//        stage 3: shuffle-reduce the buffered log partials

#define BB 2
#define LL 2048
#define HH 8
#define EE 64
#define DD 64
#define QSCALE 0.125f
#define FULL 0xffffffffu
#define KSTRIDE (HH * EE)   // 512 floats between consecutive K/V rows of same (b,h)

typedef unsigned long long u64;

__device__ __forceinline__ u64 fma2(u64 a, u64 b, u64 c) {
    u64 r; asm("fma.rn.f32x2 %0, %1, %2, %3;" : "=l"(r) : "l"(a), "l"(b), "l"(c));
    return r;
}
__device__ __forceinline__ u64 mul2(u64 a, u64 b) {
    u64 r; asm("mul.rn.f32x2 %0, %1, %2;" : "=l"(r) : "l"(a), "l"(b));
    return r;
}
__device__ __forceinline__ u64 pack2(float x, float y) {
    u64 r; asm("mov.b64 %0, {%1, %2};" : "=l"(r) : "f"(x), "f"(y));
    return r;
}
__device__ __forceinline__ void unpack2(u64 v, float& x, float& y) {
    asm("mov.b64 {%0, %1}, %2;" : "=f"(x), "=f"(y) : "l"(v));
}

__global__ __launch_bounds__(256, 4)
void logsparse_attn_kernel(const float* __restrict__ Q,
                           const float* __restrict__ K,
                           const float* __restrict__ V,
                           float* __restrict__ O)
{
    const int warp = threadIdx.x >> 5;
    const int lane = threadIdx.x & 31;
    const int sub  = lane & 7;          // chunk within row (16B units)
    const int lanebase = lane & 24;     // first lane of this 8-lane group

    const int gid   = blockIdx.x * 8 + warp;     // warp id over 8192
    const int lbase = (gid & 511) << 2;          // 512 warps per (b,h); 4 rows each
    const int bh    = gid >> 9;                  // b*H + h
    const int h     = bh & (HH - 1);
    const int b     = bh >> 3;
    const int l     = lbase + (lane >> 3);       // this group's query row
    const bool causal = (l < 22);

    const float* Kbh = K + (b * (LL * HH) + h) * EE;
    const float* Vbh = V + (b * (LL * HH) + h) * DD;

    // ---- q for own row, pre-scaled, packed ----
    const int qoff = ((b * LL + l) * HH + h) * EE;
    const ulonglong2* qp = (const ulonglong2*)(Q + qoff);
    ulonglong2 qa = qp[sub];
    ulonglong2 qb = qp[8 + sub];
    const u64 qs = pack2(QSCALE, QSCALE);
    qa.x = mul2(qa.x, qs); qa.y = mul2(qa.y, qs);
    qb.x = mul2(qb.x, qs); qb.y = mul2(qb.y, qs);

    // scores: lane holds slots {sub, sub+8, sub+16} of its row
    float s0 = -INFINITY, s1 = -INFINITY, s2 = -INFINITY;

    // ---- stage 1: log-K partial dots, NO shuffles (loads batch freely) ----
    float lp[11];
#pragma unroll
    for (int i = 0; i < 11; ++i) {
        const int j = 10 - i;
        int c;
        if (causal) { c = (j <= l) ? j : 0; }
        else        { int cc = l - 10 - (1 << i); c = (cc >= 0) ? cc : 0; }
        const ulonglong2* kp = (const ulonglong2*)(Kbh + c * KSTRIDE);
        ulonglong2 ka = kp[sub];
        ulonglong2 kb = kp[8 + sub];
        u64 d = mul2(qa.x, ka.x);
        d = fma2(qa.y, ka.y, d);
        d = fma2(qb.x, kb.x, d);
        d = fma2(qb.y, kb.y, d);
        float px, py; unpack2(d, px, py);
        lp[i] = px + py;
    }

    // ---- stage 2: window scores (cols lbase-10..lbase+3, broadcast loads) ----
#pragma unroll
    for (int t = 0; t < 14; ++t) {
        int c  = lbase - 10 + t;
        int cc = (c < 0) ? 0 : c;
        const ulonglong2* kp = (const ulonglong2*)(Kbh + cc * KSTRIDE);
        ulonglong2 ka = kp[sub];
        ulonglong2 kb = kp[8 + sub];
        int  j   = causal ? c : (c - l + 21);
        bool act = (c >= 0) && (causal ? (c <= l) : (j >= 11 && j <= 21));
        u64 d = mul2(qa.x, ka.x);
        d = fma2(qa.y, ka.y, d);
        d = fma2(qb.x, kb.x, d);
        d = fma2(qb.y, kb.y, d);
        float px, py; unpack2(d, px, py);
        float part = px + py;
        part += __shfl_xor_sync(FULL, part, 1);
        part += __shfl_xor_sync(FULL, part, 2);
        part += __shfl_xor_sync(FULL, part, 4);
        if (act && sub == (j & 7)) {
            int jr = j >> 3;
            if (jr == 0) s0 = part; else if (jr == 1) s1 = part; else s2 = part;
        }
    }

    // ---- stage 3: reduce the buffered log partials ----
#pragma unroll
    for (int i = 0; i < 11; ++i) {
        const int j = 10 - i;
        bool act;
        if (causal) act = (j <= l);
        else        act = ((l - 10 - (1 << i)) >= 0);
        float part = lp[i];
        part += __shfl_xor_sync(FULL, part, 1);
        part += __shfl_xor_sync(FULL, part, 2);
        part += __shfl_xor_sync(FULL, part, 4);
        if (act && sub == (j & 7)) {
            if ((j >> 3) == 0) s0 = part; else s1 = part;   // j <= 10
        }
    }

    // ---- per-row softmax (width-8 group reduce) ----
    float m = fmaxf(s0, fmaxf(s1, s2));
    m = fmaxf(m, __shfl_xor_sync(FULL, m, 1));
    m = fmaxf(m, __shfl_xor_sync(FULL, m, 2));
    m = fmaxf(m, __shfl_xor_sync(FULL, m, 4));
    float p0 = __expf(s0 - m), p1 = __expf(s1 - m), p2 = __expf(s2 - m);
    float sum = p0 + p1 + p2;
    sum += __shfl_xor_sync(FULL, sum, 1);
    sum += __shfl_xor_sync(FULL, sum, 2);
    sum += __shfl_xor_sync(FULL, sum, 4);
    float inv = __frcp_rn(sum);
    p0 *= inv; p1 *= inv; p2 *= inv;

    // ---- V accumulation: lane holds dims {sub*4..+3, 32+sub*4..+3} of own row ----
    u64 a00 = pack2(0.f, 0.f), a01 = a00, a10 = a00, a11 = a00;

    // window V (shared cols, broadcast loads; p=0 kills inactive slots)
#pragma unroll
    for (int t = 0; t < 14; ++t) {
        int c  = lbase - 10 + t;
        int cc = (c < 0) ? 0 : c;
        const ulonglong2* vp = (const ulonglong2*)(Vbh + cc * KSTRIDE);
        ulonglong2 va = vp[sub];
        ulonglong2 vb = vp[8 + sub];
        int  j   = causal ? c : (c - l + 21);
        bool act = (c >= 0) && (causal ? (c <= l) : (j >= 11 && j <= 21));
        int  jj  = act ? j : 0;
        int  jr  = jj >> 3;
        float psel = (jr == 0) ? p0 : ((jr == 1) ? p1 : p2);
        float pj = __shfl_sync(FULL, psel, lanebase | (jj & 7));
        pj = act ? pj : 0.0f;
        u64 pj2 = pack2(pj, pj);
        a00 = fma2(pj2, va.x, a00); a01 = fma2(pj2, va.y, a01);
        a10 = fma2(pj2, vb.x, a10); a11 = fma2(pj2, vb.y, a11);
    }

    // log V (row-private cols; causal rows deduped against the window loop)
#pragma unroll
    for (int i = 0; i < 11; ++i) {
        const int j = 10 - i;
        int c; bool act;
        if (causal) { act = (j <= l) && (j < lbase - 10); c = (j <= l) ? j : 0; }
        else        { c = l - 10 - (1 << i); act = (c >= 0); c = act ? c : 0; }
        const ulonglong2* vp = (const ulonglong2*)(Vbh + c * KSTRIDE);
        ulonglong2 va = vp[sub];
        ulonglong2 vb = vp[8 + sub];
        float psel = (j <= 7) ? p0 : p1;
        float pj = __shfl_sync(FULL, psel, lanebase | (j & 7));
        pj = act ? pj : 0.0f;
        u64 pj2 = pack2(pj, pj);
        a00 = fma2(pj2, va.x, a00); a01 = fma2(pj2, va.y, a01);
        a10 = fma2(pj2, vb.x, a10); a11 = fma2(pj2, vb.y, a11);
    }

    // ---- store own row ----
    float x0, x1, x2, x3;
    float4* op = (float4*)(O + qoff);
    unpack2(a00, x0, x1); unpack2(a01, x2, x3);
    op[sub] = make_float4(x0, x1, x2, x3);
    unpack2(a10, x0, x1); unpack2(a11, x2, x3);
    op[8 + sub] = make_float4(x0, x1, x2, x3);
}

extern "C" void kernel_launch(void* const* d_in, const int* in_sizes, int n_in,
                              void* d_out, int out_size) {
    const float* Q = (const float*)d_in[0];
    const float* K = (const float*)d_in[1];
    const float* V = (const float*)d_in[2];
    float* O = (float*)d_out;

    dim3 grid(BB * HH * (LL / 4) / 8);   // 1024 blocks, 8 warps each
    logsparse_attn_kernel<<<grid, 256>>>(Q, K, V, O);
}